// round 5
// baseline (speedup 1.0000x reference)
#include <cuda_runtime.h>
#include <math.h>

// Problem constants
#define BB 4
#define MM 500   // rows (pred2)
#define NN 500   // cols (pred1)
#define CC 91
#define NPAD 512
#define FULLMASK 0xffffffffu
#define MARGIN 1e-4f

// Scratch (device globals; no allocation allowed)
__device__ float g_s1[BB * NN * CC];   // sigmoid(pred1_logits)
__device__ float g_s2[BB * MM * CC];   // sigmoid(pred2_logits)
__device__ __align__(16) float g_cost[BB * MM * NPAD]; // padded cost rows
__device__ int   g_map[BB * MM];       // row -> col assignment

// ---------------------------------------------------------------------------
// 1) sigmoids
// ---------------------------------------------------------------------------
__global__ void sigmoid_kernel(const float* __restrict__ l1,
                               const float* __restrict__ l2) {
    int idx = blockIdx.x * blockDim.x + threadIdx.x;
    const int n1 = BB * NN * CC;
    const int n2 = BB * MM * CC;
    if (idx < n1) {
        float x = l1[idx];
        g_s1[idx] = 1.0f / (1.0f + expf(-x));
    } else if (idx < n1 + n2) {
        float x = l2[idx - n1];
        g_s2[idx - n1] = 1.0f / (1.0f + expf(-x));
    }
}

// ---------------------------------------------------------------------------
// 2) cost matrix: cost[b][i][j] = 0.5*||c2_i - c1_j||2 + 0.5*max_c|s2-s1|
// ---------------------------------------------------------------------------
__global__ __launch_bounds__(1024) void cost_kernel(
        const float* __restrict__ p1_boxes,
        const float* __restrict__ p2_boxes) {
    const int b = blockIdx.z;
    const int i0 = blockIdx.y * 32;
    const int j0 = blockIdx.x * 32;

    __shared__ float s2t[32][CC];
    __shared__ float s1t[32][CC];
    __shared__ float b2x[32], b2y[32], b1x[32], b1y[32];

    const int tx = threadIdx.x;
    const int ty = threadIdx.y;
    const int tid = ty * 32 + tx;

    for (int idx = tid; idx < 32 * CC; idx += 1024) {
        int r = idx / CC, c = idx % CC;
        int gi = i0 + r;
        int gj = j0 + r;
        s2t[r][c] = (gi < MM) ? g_s2[(b * MM + gi) * CC + c] : 0.0f;
        s1t[r][c] = (gj < NN) ? g_s1[(b * NN + gj) * CC + c] : 0.0f;
    }
    if (ty == 0) {
        int gi = i0 + tx;
        if (gi < MM) {
            b2x[tx] = p2_boxes[(b * MM + gi) * 4 + 0];
            b2y[tx] = p2_boxes[(b * MM + gi) * 4 + 1];
        }
    } else if (ty == 1) {
        int gj = j0 + tx;
        if (gj < NN) {
            b1x[tx] = p1_boxes[(b * NN + gj) * 4 + 0];
            b1y[tx] = p1_boxes[(b * NN + gj) * 4 + 1];
        }
    }
    __syncthreads();

    const int i = i0 + ty;
    const int j = j0 + tx;
    if (i < MM) {
        if (j < NN) {
            float mx = 0.0f;
            #pragma unroll
            for (int c = 0; c < CC; c++) {
                mx = fmaxf(mx, fabsf(s2t[ty][c] - s1t[tx][c]));
            }
            float dx = __fadd_rn(b2x[ty], -b1x[tx]);
            float dy = __fadd_rn(b2y[ty], -b1y[tx]);
            float cd = __fsqrt_rn(__fadd_rn(__fmul_rn(dx, dx), __fmul_rn(dy, dy)));
            g_cost[(b * MM + i) * NPAD + j] =
                __fadd_rn(__fmul_rn(0.5f, cd), __fmul_rn(0.5f, mx));
        } else {
            g_cost[(b * MM + i) * NPAD + j] = 1e30f;  // padding
        }
    }
}

// ---------------------------------------------------------------------------
// 3) exact LSA (shortest augmenting path, scipy rectangular_lsap semantics)
//    one warp per batch. Register-resident per-lane state:
//      vreg[16]  fp32 shadow of v64 (constant within a round)
//      seM[16]   shortest32 + MARGIN (FINF when untouched)
//      keys[16]  packed (bits(shortest32+1.0) & ~0x1ff) | col  (MAX when none)
//      rem       bitmask of not-yet-scanned owned columns  <-- gates candidates
//    fp64 exact values live in shared (s64s/v64s/u64s) and are touched only
//    on margin-candidates, keeping scipy-faithful selection + duals.
// ---------------------------------------------------------------------------
__global__ __launch_bounds__(32) void lsa_kernel() {
    const int b = blockIdx.x;
    const int lane = threadIdx.x;
    const double DINF = __longlong_as_double(0x7ff0000000000000LL);
    const float  FINF = __int_as_float(0x7f800000);

    __shared__ double u64s[MM];
    __shared__ double v64s[NPAD];
    __shared__ double s64s[NPAD];
    __shared__ float u32s[MM];
    __shared__ int paths[NPAD];
    __shared__ int col4rows[MM];
    __shared__ int row4cols[NPAD];
    __shared__ int SRs[MM];

    for (int t = lane; t < NPAD; t += 32) {
        v64s[t] = 0.0; row4cols[t] = -1;
        if (t < MM) { u64s[t] = 0.0; u32s[t] = 0.0f; col4rows[t] = -1; }
    }
    const int base = lane * 16;
    unsigned validMask;
    {
        int nvalid = NN - base;
        if (nvalid < 0) nvalid = 0;
        if (nvalid > 16) nvalid = 16;
        validMask = (nvalid == 16) ? 0xffffu : ((1u << nvalid) - 1u);
    }
    float vreg[16];
    #pragma unroll
    for (int kk = 0; kk < 16; kk++) vreg[kk] = 0.0f;
    __syncwarp();

    const float* costB = g_cost + (size_t)b * MM * NPAD;

    for (int cur = 0; cur < MM; cur++) {
        float seM[16];
        unsigned keys[16];
        #pragma unroll
        for (int kk = 0; kk < 16; kk++) {
            seM[kk] = FINF;
            keys[kk] = 0xffffffffu;
        }
        unsigned rem = validMask;     // not-yet-scanned owned columns
        unsigned scanned = 0;
        double minv = 0.0;
        float minv32 = 0.0f;
        int i = cur;
        int nSR = 0;
        int sink = -1;
        __syncwarp();

        while (true) {
            if (lane == 0) SRs[nSR] = i;
            nSR++;
            float dd32 = minv32 - u32s[i];
            const float* crow = costB + (size_t)i * NPAD + base;

            float4 c4[4];
            c4[0] = __ldg((const float4*)(crow + 0));
            c4[1] = __ldg((const float4*)(crow + 4));
            c4[2] = __ldg((const float4*)(crow + 8));
            c4[3] = __ldg((const float4*)(crow + 12));
            float c[16];
            c[0]  = c4[0].x; c[1]  = c4[0].y; c[2]  = c4[0].z; c[3]  = c4[0].w;
            c[4]  = c4[1].x; c[5]  = c4[1].y; c[6]  = c4[1].z; c[7]  = c4[1].w;
            c[8]  = c4[2].x; c[9]  = c4[2].y; c[10] = c4[2].z; c[11] = c4[2].w;
            c[12] = c4[3].x; c[13] = c4[3].y; c[14] = c4[3].z; c[15] = c4[3].w;

            // fp32 sweep: candidate = fp32 r maybe-below current shortest+MARGIN
            unsigned candMask = 0;
            #pragma unroll
            for (int kk = 0; kk < 16; kk++) {
                float r = (c[kk] - vreg[kk]) + dd32;
                if (r < seM[kk]) candMask |= (1u << kk);
            }
            candMask &= rem;          // gate out scanned / invalid columns

            // exact fp64 updates for candidates only
            if (candMask) {
                double dd = minv - u64s[i];
                do {
                    int kk = __ffs(candMask) - 1;
                    candMask &= candMask - 1;
                    int j = base + kk;
                    double r = ((double)c[kk] - v64s[j]) + dd;
                    if (keys[kk] == 0xffffffffu) {
                        s64s[j] = r;            // first touch this round
                    } else if (r < s64s[j]) {
                        s64s[j] = r;
                    } else {
                        continue;
                    }
                    float rf = (float)r;
                    seM[kk] = rf + MARGIN;
                    unsigned ub = __float_as_uint(rf + 1.0f);
                    keys[kk] = (ub & 0xfffffe00u) | (unsigned)j;
                    paths[j] = i;
                } while (candMask);
            }

            // warp-local min key via register tree, then one REDUX
            unsigned bk01 = min(keys[0], keys[1]);
            unsigned bk23 = min(keys[2], keys[3]);
            unsigned bk45 = min(keys[4], keys[5]);
            unsigned bk67 = min(keys[6], keys[7]);
            unsigned bk89 = min(keys[8], keys[9]);
            unsigned bkAB = min(keys[10], keys[11]);
            unsigned bkCD = min(keys[12], keys[13]);
            unsigned bkEF = min(keys[14], keys[15]);
            unsigned bk = min(min(min(bk01, bk23), min(bk45, bk67)),
                              min(min(bk89, bkAB), min(bkCD, bkEF)));
            unsigned mk = __reduce_min_sync(FULLMASK, bk);

            // speculative prefetch of the likely next row (own segment)
            int jm_a = (int)(mk & 0x1ffu);
            int i_next = row4cols[jm_a];
            if (i_next >= 0) {
                const float* pf = costB + (size_t)i_next * NPAD + base;
                asm volatile("prefetch.global.L1 [%0];" :: "l"(pf));
            }

            // threshold key: decoded truncated min + slack (covers 9-bit key
            // quantization <=2.4e-4 and fp32 shadow error <=1e-6, plus MARGIN)
            float dec = __uint_as_float(mk & 0xfffffe00u);
            float thrp = dec + 1e-3f;
            unsigned thrKey = (__float_as_uint(thrp) & 0xfffffe00u) | 0x1ffu;

            // exact resolution among columns within threshold
            double bestV = DINF;
            int bestJ = 0x7fffffff;
            if (bk <= thrKey) {
                unsigned resMask = 0;
                #pragma unroll
                for (int kk = 0; kk < 16; kk++) {
                    if (keys[kk] <= thrKey) resMask |= (1u << kk);
                }
                while (resMask) {
                    int kk = __ffs(resMask) - 1;
                    resMask &= resMask - 1;
                    int j = base + kk;
                    double sv = s64s[j];
                    if (sv < bestV) { bestV = sv; bestJ = j; }  // ascending j
                }
            }
            unsigned bal = __ballot_sync(FULLMASK, bestJ != 0x7fffffff);
            int jm;
            if (__popc(bal) == 1) {
                int src = __ffs(bal) - 1;
                minv = __shfl_sync(FULLMASK, bestV, src);
                jm   = __shfl_sync(FULLMASK, bestJ, src);
            } else {
                #pragma unroll
                for (int off = 16; off > 0; off >>= 1) {
                    double ov = __shfl_down_sync(FULLMASK, bestV, off);
                    int    oj = __shfl_down_sync(FULLMASK, bestJ, off);
                    if (ov < bestV || (ov == bestV && oj < bestJ)) { bestV = ov; bestJ = oj; }
                }
                minv = __shfl_sync(FULLMASK, bestV, 0);
                jm   = __shfl_sync(FULLMASK, bestJ, 0);
            }
            if (jm > 0x1ff) { sink = -1; break; }   // impossible-by-construction guard
            minv32 = (float)minv;
            // remove column jm (owner lane: registers only)
            if (lane == (jm >> 4)) {
                int kk = jm & 15;
                rem &= ~(1u << kk);
                scanned |= (1u << kk);
                seM[kk] = FINF;
                keys[kk] = 0xffffffffu;
            }
            int r4c = row4cols[jm];   // shared broadcast
            if (r4c < 0) { sink = jm; break; }
            i = r4c;
        }
        __syncwarp();
        if (sink < 0) continue;       // guard path (never taken in valid runs)

        // dual updates (exact fp64, scipy order)
        for (int s = lane; s < nSR; s += 32) {
            int row = SRs[s];
            double nu = u64s[row] +
                        ((s == 0) ? minv : (minv - s64s[col4rows[row]]));
            u64s[row] = nu;
            u32s[row] = (float)nu;
        }
        {
            unsigned sm2 = scanned;
            while (sm2) {
                int kk = __ffs(sm2) - 1;
                sm2 &= sm2 - 1;
                int j = base + kk;
                double nv = v64s[j] - (minv - s64s[j]);
                v64s[j] = nv;
                vreg[kk] = (float)nv;
            }
        }
        __syncwarp();
        if (lane == 0) {
            int j = sink;
            while (true) {
                int ii = paths[j];
                row4cols[j] = ii;
                int t = col4rows[ii];
                col4rows[ii] = j;
                j = t;
                if (ii == cur) break;
            }
        }
        __syncwarp();
    }

    for (int t = lane; t < MM; t += 32) g_map[b * MM + t] = col4rows[t];
}

// ---------------------------------------------------------------------------
// 4) extrapolation + output write
// ---------------------------------------------------------------------------
__global__ void extrap_kernel(const float* __restrict__ p1_boxes,
                              const float* __restrict__ p1_logits,
                              const float* __restrict__ p2_boxes,
                              const float* __restrict__ p2_logits,
                              const float* __restrict__ toff,
                              float* __restrict__ out) {
    int idx = blockIdx.x * blockDim.x + threadIdx.x;
    const int boxTotal = BB * MM * 4;
    const int logTotal = BB * MM * CC;
    if (idx < boxTotal) {
        int d = idx & 3;
        int bi = idx >> 2;
        int b = bi / MM;
        float first  = toff[b * 3 + 1] - toff[b * 3 + 0];
        float second = toff[b * 3 + 2] - toff[b * 3 + 1];
        float factor = second / first;
        int mcol = g_map[bi];
        float b2 = p2_boxes[idx];
        float c1 = p1_boxes[(b * NN + mcol) * 4 + d];
        float val = b2 + (b2 - c1) * factor;
        if (d >= 2) val = fmaxf(val, 0.0f);
        out[idx] = val;
    } else if (idx < boxTotal + logTotal) {
        int t = idx - boxTotal;
        int c = t % CC;
        int bi = t / CC;
        int b = bi / MM;
        int mcol = g_map[bi];
        float l2 = p2_logits[t];
        float l1 = p1_logits[(b * NN + mcol) * CC + c];
        out[idx] = 0.5f * (l2 + l1);
    }
}

// ---------------------------------------------------------------------------
extern "C" void kernel_launch(void* const* d_in, const int* in_sizes, int n_in,
                              void* d_out, int out_size) {
    const float* p1_boxes  = (const float*)d_in[0];
    const float* p1_logits = (const float*)d_in[1];
    const float* p2_boxes  = (const float*)d_in[2];
    const float* p2_logits = (const float*)d_in[3];
    const float* toff      = (const float*)d_in[4];
    float* out = (float*)d_out;

    {
        int total = BB * NN * CC + BB * MM * CC;
        int threads = 256;
        int blocks = (total + threads - 1) / threads;
        sigmoid_kernel<<<blocks, threads>>>(p1_logits, p2_logits);
    }
    {
        dim3 grid(NPAD / 32, (MM + 31) / 32, BB);
        dim3 block(32, 32);
        cost_kernel<<<grid, block>>>(p1_boxes, p2_boxes);
    }
    lsa_kernel<<<BB, 32>>>();
    {
        int total = BB * MM * 4 + BB * MM * CC;
        int threads = 256;
        int blocks = (total + threads - 1) / threads;
        extrap_kernel<<<blocks, threads>>>(p1_boxes, p1_logits, p2_boxes,
                                           p2_logits, toff, out);
    }
}

// round 6
// speedup vs baseline: 1.1836x; 1.1836x over previous
#include <cuda_runtime.h>
#include <math.h>

// Problem constants
#define BB 4
#define MM 500   // rows (pred2)
#define NN 500   // cols (pred1)
#define CC 91
#define NPAD 512
#define FULLMASK 0xffffffffu
#define MARGIN 1e-4f

// Scratch (device globals; no allocation allowed)
__device__ float g_s1[BB * NN * CC];   // sigmoid(pred1_logits)
__device__ float g_s2[BB * MM * CC];   // sigmoid(pred2_logits)
__device__ __align__(16) float g_cost[BB * MM * NPAD]; // padded cost rows
__device__ int   g_map[BB * MM];       // row -> col assignment

// ---------------------------------------------------------------------------
// 1) sigmoids
// ---------------------------------------------------------------------------
__global__ void sigmoid_kernel(const float* __restrict__ l1,
                               const float* __restrict__ l2) {
    int idx = blockIdx.x * blockDim.x + threadIdx.x;
    const int n1 = BB * NN * CC;
    const int n2 = BB * MM * CC;
    if (idx < n1) {
        float x = l1[idx];
        g_s1[idx] = 1.0f / (1.0f + expf(-x));
    } else if (idx < n1 + n2) {
        float x = l2[idx - n1];
        g_s2[idx - n1] = 1.0f / (1.0f + expf(-x));
    }
}

// ---------------------------------------------------------------------------
// 2) cost matrix: cost[b][i][j] = 0.5*||c2_i - c1_j||2 + 0.5*max_c|s2-s1|
// ---------------------------------------------------------------------------
__global__ __launch_bounds__(1024) void cost_kernel(
        const float* __restrict__ p1_boxes,
        const float* __restrict__ p2_boxes) {
    const int b = blockIdx.z;
    const int i0 = blockIdx.y * 32;
    const int j0 = blockIdx.x * 32;

    __shared__ float s2t[32][CC];
    __shared__ float s1t[32][CC];
    __shared__ float b2x[32], b2y[32], b1x[32], b1y[32];

    const int tx = threadIdx.x;
    const int ty = threadIdx.y;
    const int tid = ty * 32 + tx;

    for (int idx = tid; idx < 32 * CC; idx += 1024) {
        int r = idx / CC, c = idx % CC;
        int gi = i0 + r;
        int gj = j0 + r;
        s2t[r][c] = (gi < MM) ? g_s2[(b * MM + gi) * CC + c] : 0.0f;
        s1t[r][c] = (gj < NN) ? g_s1[(b * NN + gj) * CC + c] : 0.0f;
    }
    if (ty == 0) {
        int gi = i0 + tx;
        if (gi < MM) {
            b2x[tx] = p2_boxes[(b * MM + gi) * 4 + 0];
            b2y[tx] = p2_boxes[(b * MM + gi) * 4 + 1];
        }
    } else if (ty == 1) {
        int gj = j0 + tx;
        if (gj < NN) {
            b1x[tx] = p1_boxes[(b * NN + gj) * 4 + 0];
            b1y[tx] = p1_boxes[(b * NN + gj) * 4 + 1];
        }
    }
    __syncthreads();

    const int i = i0 + ty;
    const int j = j0 + tx;
    if (i < MM) {
        if (j < NN) {
            float mx = 0.0f;
            #pragma unroll
            for (int c = 0; c < CC; c++) {
                mx = fmaxf(mx, fabsf(s2t[ty][c] - s1t[tx][c]));
            }
            float dx = __fadd_rn(b2x[ty], -b1x[tx]);
            float dy = __fadd_rn(b2y[ty], -b1y[tx]);
            float cd = __fsqrt_rn(__fadd_rn(__fmul_rn(dx, dx), __fmul_rn(dy, dy)));
            g_cost[(b * MM + i) * NPAD + j] =
                __fadd_rn(__fmul_rn(0.5f, cd), __fmul_rn(0.5f, mx));
        } else {
            g_cost[(b * MM + i) * NPAD + j] = 1e30f;  // padding
        }
    }
}

// ---------------------------------------------------------------------------
// 3) exact LSA (shortest augmenting path, scipy rectangular_lsap semantics)
//    one warp per batch; lane L owns columns [L*16, L*16+16).
//    Shared per-column state (dynamically indexed -> must be shared):
//      tshared[j] = v32[j] + s32[j] + MARGIN   (gate; -inf = removed/invalid)
//      keysh[j]   = (bits(s32+1.0) & ~0x1ff) | j  (MAX = untouched/removed)
//      s64s/v64s/u64s/paths: exact fp64 state, scipy-faithful.
//    Register arrays are only accessed with compile-time indices (no spills).
// ---------------------------------------------------------------------------
__global__ __launch_bounds__(32) void lsa_kernel() {
    const int b = blockIdx.x;
    const int lane = threadIdx.x;
    const double DINF = __longlong_as_double(0x7ff0000000000000LL);
    const float  FINF = __int_as_float(0x7f800000);
    const float  FNINF = __int_as_float(0xff800000);

    __shared__ double u64s[MM];
    __shared__ double v64s[NPAD];
    __shared__ double s64s[NPAD];
    __shared__ float u32s[MM];
    __shared__ __align__(16) float v32s[NPAD];
    __shared__ __align__(16) float tshared[NPAD];
    __shared__ __align__(16) unsigned keysh[NPAD];
    __shared__ int paths[NPAD];
    __shared__ int col4rows[MM];
    __shared__ int row4cols[NPAD];
    __shared__ int SRs[MM];

    for (int t = lane; t < NPAD; t += 32) {
        v64s[t] = 0.0; v32s[t] = 0.0f; row4cols[t] = -1;
        if (t < MM) { u64s[t] = 0.0; u32s[t] = 0.0f; col4rows[t] = -1; }
    }
    const int base = lane * 16;
    unsigned validMask;
    {
        int nvalid = NN - base;
        if (nvalid < 0) nvalid = 0;
        if (nvalid > 16) nvalid = 16;
        validMask = (nvalid == 16) ? 0xffffu : ((1u << nvalid) - 1u);
    }
    __syncwarp();

    const float* costB = g_cost + (size_t)b * MM * NPAD;

    for (int cur = 0; cur < MM; cur++) {
        // round init of own segment (constant indices only)
        #pragma unroll
        for (int kk = 0; kk < 16; kk++) {
            tshared[base + kk] = ((validMask >> kk) & 1u) ? FINF : FNINF;
            keysh[base + kk] = 0xffffffffu;
            s64s[base + kk] = DINF;
        }
        unsigned scanned = 0;
        double minv = 0.0;
        float minv32 = 0.0f;
        int i = cur;
        int nSR = 0;
        int sink = -1;
        __syncwarp();

        while (true) {
            if (lane == 0) SRs[nSR] = i;
            nSR++;
            float dd32 = minv32 - u32s[i];
            const float* crow = costB + (size_t)i * NPAD + base;

            // load cost segment (global) and gate segment (shared)
            float4 ca = __ldg((const float4*)(crow + 0));
            float4 cb = __ldg((const float4*)(crow + 4));
            float4 cc_ = __ldg((const float4*)(crow + 8));
            float4 cd = __ldg((const float4*)(crow + 12));
            float4 ta = *(const float4*)(tshared + base + 0);
            float4 tb = *(const float4*)(tshared + base + 4);
            float4 tc = *(const float4*)(tshared + base + 8);
            float4 td = *(const float4*)(tshared + base + 12);

            // fp32 gate sweep: (c + dd32) < t
            unsigned candMask = 0;
            if (ca.x + dd32 < ta.x) candMask |= 1u << 0;
            if (ca.y + dd32 < ta.y) candMask |= 1u << 1;
            if (ca.z + dd32 < ta.z) candMask |= 1u << 2;
            if (ca.w + dd32 < ta.w) candMask |= 1u << 3;
            if (cb.x + dd32 < tb.x) candMask |= 1u << 4;
            if (cb.y + dd32 < tb.y) candMask |= 1u << 5;
            if (cb.z + dd32 < tb.z) candMask |= 1u << 6;
            if (cb.w + dd32 < tb.w) candMask |= 1u << 7;
            if (cc_.x + dd32 < tc.x) candMask |= 1u << 8;
            if (cc_.y + dd32 < tc.y) candMask |= 1u << 9;
            if (cc_.z + dd32 < tc.z) candMask |= 1u << 10;
            if (cc_.w + dd32 < tc.w) candMask |= 1u << 11;
            if (cd.x + dd32 < td.x) candMask |= 1u << 12;
            if (cd.y + dd32 < td.y) candMask |= 1u << 13;
            if (cd.z + dd32 < td.z) candMask |= 1u << 14;
            if (cd.w + dd32 < td.w) candMask |= 1u << 15;

            // exact fp64 updates for candidates (dynamic indices -> shared/global only)
            if (candMask) {
                double dd = minv - u64s[i];
                do {
                    int kk = __ffs(candMask) - 1;
                    candMask &= candMask - 1;
                    int j = base + kk;
                    double r = ((double)__ldg(crow + kk) - v64s[j]) + dd;
                    if (r < s64s[j]) {
                        s64s[j] = r;
                        paths[j] = i;
                        float rf = (float)r;
                        unsigned ub = __float_as_uint(rf + 1.0f);
                        keysh[j] = (ub & 0xfffffe00u) | (unsigned)j;
                        tshared[j] = v32s[j] + (rf + MARGIN);
                    }
                } while (candMask);
            }

            // reload own keys (constant indices), warp min via tree + REDUX
            uint4 k0 = *(const uint4*)(keysh + base + 0);
            uint4 k1 = *(const uint4*)(keysh + base + 4);
            uint4 k2 = *(const uint4*)(keysh + base + 8);
            uint4 k3 = *(const uint4*)(keysh + base + 12);
            unsigned bk = min(min(min(min(k0.x, k0.y), min(k0.z, k0.w)),
                                  min(min(k1.x, k1.y), min(k1.z, k1.w))),
                              min(min(min(k2.x, k2.y), min(k2.z, k2.w)),
                                  min(min(k3.x, k3.y), min(k3.z, k3.w))));
            unsigned mk = __reduce_min_sync(FULLMASK, bk);
            if (mk == 0xffffffffu) { sink = -1; break; }  // defensive

            // approximate argmin column; prefetch its row (own segment)
            int jm_a = (int)(mk & 0x1ffu);
            int r4c_a = row4cols[jm_a];
            if (r4c_a >= 0) {
                const float* pf = costB + (size_t)r4c_a * NPAD + base;
                asm volatile("prefetch.global.L1 [%0];" :: "l"(pf));
            }

            // threshold window (covers 9-bit key quantization + fp32 error + MARGIN)
            float dec = __uint_as_float(mk & 0xfffffe00u);
            unsigned thrKey = (__float_as_uint(dec + 1e-3f) & 0xfffffe00u) | 0x1ffu;

            unsigned resMask = 0;
            if (k0.x <= thrKey) resMask |= 1u << 0;
            if (k0.y <= thrKey) resMask |= 1u << 1;
            if (k0.z <= thrKey) resMask |= 1u << 2;
            if (k0.w <= thrKey) resMask |= 1u << 3;
            if (k1.x <= thrKey) resMask |= 1u << 4;
            if (k1.y <= thrKey) resMask |= 1u << 5;
            if (k1.z <= thrKey) resMask |= 1u << 6;
            if (k1.w <= thrKey) resMask |= 1u << 7;
            if (k2.x <= thrKey) resMask |= 1u << 8;
            if (k2.y <= thrKey) resMask |= 1u << 9;
            if (k2.z <= thrKey) resMask |= 1u << 10;
            if (k2.w <= thrKey) resMask |= 1u << 11;
            if (k3.x <= thrKey) resMask |= 1u << 12;
            if (k3.y <= thrKey) resMask |= 1u << 13;
            if (k3.z <= thrKey) resMask |= 1u << 14;
            if (k3.w <= thrKey) resMask |= 1u << 15;

            unsigned bal1 = __ballot_sync(FULLMASK, resMask != 0);
            unsigned balM = __ballot_sync(FULLMASK, __popc(resMask) > 1);
            int jm;
            int r4c;
            if (balM == 0 && __popc(bal1) == 1) {
                // fast path: unique window candidate == approximate argmin
                jm = jm_a;
                double myv = s64s[base + (jm_a & 15)];   // own-segment read
                minv = __shfl_sync(FULLMASK, myv, jm_a >> 4);
                r4c = r4c_a;
            } else {
                // slow path: exact fp64 resolution (scipy first-index tie-break)
                double bestV = DINF;
                int bestJ = 0x7fffffff;
                unsigned rm = resMask;
                while (rm) {
                    int kk = __ffs(rm) - 1;
                    rm &= rm - 1;
                    int j = base + kk;
                    double sv = s64s[j];
                    if (sv < bestV) { bestV = sv; bestJ = j; }  // ascending j
                }
                #pragma unroll
                for (int off = 16; off > 0; off >>= 1) {
                    double ov = __shfl_down_sync(FULLMASK, bestV, off);
                    int    oj = __shfl_down_sync(FULLMASK, bestJ, off);
                    if (ov < bestV || (ov == bestV && oj < bestJ)) { bestV = ov; bestJ = oj; }
                }
                minv = __shfl_sync(FULLMASK, bestV, 0);
                jm   = __shfl_sync(FULLMASK, bestJ, 0);
                if (jm > 0x1ff) { sink = -1; break; }   // defensive
                r4c = row4cols[jm];
            }
            minv32 = (float)minv;
            // remove column jm (owner lane)
            if (lane == (jm >> 4)) {
                int kk = jm & 15;
                scanned |= (1u << kk);
                tshared[jm] = FNINF;
                keysh[jm] = 0xffffffffu;
            }
            if (r4c < 0) { sink = jm; break; }
            i = r4c;
        }
        __syncwarp();
        if (sink < 0) continue;       // defensive (never taken in valid runs)

        // dual updates (exact fp64, scipy order)
        for (int s = lane; s < nSR; s += 32) {
            int row = SRs[s];
            double nu = u64s[row] +
                        ((s == 0) ? minv : (minv - s64s[col4rows[row]]));
            u64s[row] = nu;
            u32s[row] = (float)nu;
        }
        {
            unsigned sm2 = scanned;
            while (sm2) {
                int kk = __ffs(sm2) - 1;
                sm2 &= sm2 - 1;
                int j = base + kk;
                double nv = v64s[j] - (minv - s64s[j]);
                v64s[j] = nv;
                v32s[j] = (float)nv;
            }
        }
        __syncwarp();
        if (lane == 0) {
            int j = sink;
            while (true) {
                int ii = paths[j];
                row4cols[j] = ii;
                int t = col4rows[ii];
                col4rows[ii] = j;
                j = t;
                if (ii == cur) break;
            }
        }
        __syncwarp();
    }

    for (int t = lane; t < MM; t += 32) g_map[b * MM + t] = col4rows[t];
}

// ---------------------------------------------------------------------------
// 4) extrapolation + output write
// ---------------------------------------------------------------------------
__global__ void extrap_kernel(const float* __restrict__ p1_boxes,
                              const float* __restrict__ p1_logits,
                              const float* __restrict__ p2_boxes,
                              const float* __restrict__ p2_logits,
                              const float* __restrict__ toff,
                              float* __restrict__ out) {
    int idx = blockIdx.x * blockDim.x + threadIdx.x;
    const int boxTotal = BB * MM * 4;
    const int logTotal = BB * MM * CC;
    if (idx < boxTotal) {
        int d = idx & 3;
        int bi = idx >> 2;
        int b = bi / MM;
        float first  = toff[b * 3 + 1] - toff[b * 3 + 0];
        float second = toff[b * 3 + 2] - toff[b * 3 + 1];
        float factor = second / first;
        int mcol = g_map[bi];
        float b2 = p2_boxes[idx];
        float c1 = p1_boxes[(b * NN + mcol) * 4 + d];
        float val = b2 + (b2 - c1) * factor;
        if (d >= 2) val = fmaxf(val, 0.0f);
        out[idx] = val;
    } else if (idx < boxTotal + logTotal) {
        int t = idx - boxTotal;
        int c = t % CC;
        int bi = t / CC;
        int b = bi / MM;
        int mcol = g_map[bi];
        float l2 = p2_logits[t];
        float l1 = p1_logits[(b * NN + mcol) * CC + c];
        out[idx] = 0.5f * (l2 + l1);
    }
}

// ---------------------------------------------------------------------------
extern "C" void kernel_launch(void* const* d_in, const int* in_sizes, int n_in,
                              void* d_out, int out_size) {
    const float* p1_boxes  = (const float*)d_in[0];
    const float* p1_logits = (const float*)d_in[1];
    const float* p2_boxes  = (const float*)d_in[2];
    const float* p2_logits = (const float*)d_in[3];
    const float* toff      = (const float*)d_in[4];
    float* out = (float*)d_out;

    {
        int total = BB * NN * CC + BB * MM * CC;
        int threads = 256;
        int blocks = (total + threads - 1) / threads;
        sigmoid_kernel<<<blocks, threads>>>(p1_logits, p2_logits);
    }
    {
        dim3 grid(NPAD / 32, (MM + 31) / 32, BB);
        dim3 block(32, 32);
        cost_kernel<<<grid, block>>>(p1_boxes, p2_boxes);
    }
    lsa_kernel<<<BB, 32>>>();
    {
        int total = BB * MM * 4 + BB * MM * CC;
        int threads = 256;
        int blocks = (total + threads - 1) / threads;
        extrap_kernel<<<blocks, threads>>>(p1_boxes, p1_logits, p2_boxes,
                                           p2_logits, toff, out);
    }
}

// round 8
// speedup vs baseline: 1.5903x; 1.3437x over previous
#include <cuda_runtime.h>
#include <math.h>

// Problem constants
#define BB 4
#define MM 500   // rows (pred2)
#define NN 500   // cols (pred1)
#define CC 91
#define NPAD 512
#define FULLMASK 0xffffffffu
#define MARGIN 1e-4f

// Scratch (device globals; no allocation allowed)
__device__ float g_s1[BB * NN * CC];   // sigmoid(pred1_logits)
__device__ float g_s2[BB * MM * CC];   // sigmoid(pred2_logits)
__device__ __align__(16) float g_cost[BB * MM * NPAD]; // padded cost rows
__device__ int   g_map[BB * MM];       // row -> col assignment

// ---------------------------------------------------------------------------
// 1) sigmoids
// ---------------------------------------------------------------------------
__global__ void sigmoid_kernel(const float* __restrict__ l1,
                               const float* __restrict__ l2) {
    int idx = blockIdx.x * blockDim.x + threadIdx.x;
    const int n1 = BB * NN * CC;
    const int n2 = BB * MM * CC;
    if (idx < n1) {
        float x = l1[idx];
        g_s1[idx] = 1.0f / (1.0f + expf(-x));
    } else if (idx < n1 + n2) {
        float x = l2[idx - n1];
        g_s2[idx - n1] = 1.0f / (1.0f + expf(-x));
    }
}

// ---------------------------------------------------------------------------
// 2) cost matrix: cost[b][i][j] = 0.5*||c2_i - c1_j||2 + 0.5*max_c|s2-s1|
// ---------------------------------------------------------------------------
__global__ __launch_bounds__(1024) void cost_kernel(
        const float* __restrict__ p1_boxes,
        const float* __restrict__ p2_boxes) {
    const int b = blockIdx.z;
    const int i0 = blockIdx.y * 32;
    const int j0 = blockIdx.x * 32;

    __shared__ float s2t[32][CC];
    __shared__ float s1t[32][CC];
    __shared__ float b2x[32], b2y[32], b1x[32], b1y[32];

    const int tx = threadIdx.x;
    const int ty = threadIdx.y;
    const int tid = ty * 32 + tx;

    for (int idx = tid; idx < 32 * CC; idx += 1024) {
        int r = idx / CC, c = idx % CC;
        int gi = i0 + r;
        int gj = j0 + r;
        s2t[r][c] = (gi < MM) ? g_s2[(b * MM + gi) * CC + c] : 0.0f;
        s1t[r][c] = (gj < NN) ? g_s1[(b * NN + gj) * CC + c] : 0.0f;
    }
    if (ty == 0) {
        int gi = i0 + tx;
        if (gi < MM) {
            b2x[tx] = p2_boxes[(b * MM + gi) * 4 + 0];
            b2y[tx] = p2_boxes[(b * MM + gi) * 4 + 1];
        }
    } else if (ty == 1) {
        int gj = j0 + tx;
        if (gj < NN) {
            b1x[tx] = p1_boxes[(b * NN + gj) * 4 + 0];
            b1y[tx] = p1_boxes[(b * NN + gj) * 4 + 1];
        }
    }
    __syncthreads();

    const int i = i0 + ty;
    const int j = j0 + tx;
    if (i < MM) {
        if (j < NN) {
            float mx = 0.0f;
            #pragma unroll
            for (int c = 0; c < CC; c++) {
                mx = fmaxf(mx, fabsf(s2t[ty][c] - s1t[tx][c]));
            }
            float dx = __fadd_rn(b2x[ty], -b1x[tx]);
            float dy = __fadd_rn(b2y[ty], -b1y[tx]);
            float cd = __fsqrt_rn(__fadd_rn(__fmul_rn(dx, dx), __fmul_rn(dy, dy)));
            g_cost[(b * MM + i) * NPAD + j] =
                __fadd_rn(__fmul_rn(0.5f, cd), __fmul_rn(0.5f, mx));
        } else {
            g_cost[(b * MM + i) * NPAD + j] = 1e30f;  // padding
        }
    }
}

// ---------------------------------------------------------------------------
// 3) exact LSA: column reduction (exact duals, u == 0 everywhere) +
//    shortest-augmenting-path Dijkstra for remaining free rows.
//    One warp per batch; lane L owns columns [L*16, L*16+16).
//    v[j] = min_i c[i][j] is an exact fp32 value -> fp64 conversion exact;
//    matched reduced costs are exactly 0, all reduced costs exactly >= 0,
//    so the Dijkstra phase (identical to the round-6 passing kernel) returns
//    the optimal assignment == reference assignment (unique optimum).
// ---------------------------------------------------------------------------
__global__ __launch_bounds__(32) void lsa_kernel() {
    const int b = blockIdx.x;
    const int lane = threadIdx.x;
    const double DINF = __longlong_as_double(0x7ff0000000000000LL);
    const float  FINF = __int_as_float(0x7f800000);
    const float  FNINF = __int_as_float(0xff800000);

    __shared__ double u64s[MM];
    __shared__ double v64s[NPAD];
    __shared__ double s64s[NPAD];
    __shared__ float u32s[MM];
    __shared__ __align__(16) float v32s[NPAD];
    __shared__ __align__(16) float tshared[NPAD];
    __shared__ __align__(16) unsigned keysh[NPAD];
    __shared__ int paths[NPAD];
    __shared__ int col4rows[MM];
    __shared__ int row4cols[NPAD];
    __shared__ int SRs[MM];
    __shared__ int freeL[MM];
    __shared__ int sh_nf;

    for (int t = lane; t < NPAD; t += 32) {
        v64s[t] = 0.0; v32s[t] = 0.0f; row4cols[t] = -1;
        if (t < MM) { u64s[t] = 0.0; u32s[t] = 0.0f; col4rows[t] = -1; }
    }
    const int base = lane * 16;
    unsigned validMask;
    {
        int nvalid = NN - base;
        if (nvalid < 0) nvalid = 0;
        if (nvalid > 16) nvalid = 16;
        validMask = (nvalid == 16) ? 0xffffu : ((1u << nvalid) - 1u);
    }
    __syncwarp();

    const float* costB = g_cost + (size_t)b * MM * NPAD;

    // ------------------- Phase A: column reduction --------------------------
    {
        float vmin[16];
        int imin[16];
        #pragma unroll
        for (int kk = 0; kk < 16; kk++) { vmin[kk] = FINF; imin[kk] = 0; }
        for (int i = 0; i < MM; i++) {
            const float* crow = costB + (size_t)i * NPAD + base;
            float4 ca = __ldg((const float4*)(crow + 0));
            float4 cb = __ldg((const float4*)(crow + 4));
            float4 cc_ = __ldg((const float4*)(crow + 8));
            float4 cd = __ldg((const float4*)(crow + 12));
            float c[16];
            c[0]=ca.x; c[1]=ca.y; c[2]=ca.z; c[3]=ca.w;
            c[4]=cb.x; c[5]=cb.y; c[6]=cb.z; c[7]=cb.w;
            c[8]=cc_.x; c[9]=cc_.y; c[10]=cc_.z; c[11]=cc_.w;
            c[12]=cd.x; c[13]=cd.y; c[14]=cd.z; c[15]=cd.w;
            #pragma unroll
            for (int kk = 0; kk < 16; kk++) {
                if (c[kk] < vmin[kk]) { vmin[kk] = c[kk]; imin[kk] = i; }
            }
        }
        #pragma unroll
        for (int kk = 0; kk < 16; kk++) {
            int j = base + kk;
            if ((validMask >> kk) & 1u) {
                v64s[j] = (double)vmin[kk];   // exact
                v32s[j] = vmin[kk];
                paths[j] = imin[kk];          // temp: argmin row per column
            }
        }
        __syncwarp();
        if (lane == 0) {
            for (int j = NN - 1; j >= 0; j--) {
                int i1 = paths[j];
                if (col4rows[i1] == -1) {
                    col4rows[i1] = j;
                    row4cols[j] = i1;
                }
            }
            // build free-row list
            int nf = 0;
            for (int i2 = 0; i2 < MM; i2++)
                if (col4rows[i2] < 0) freeL[nf++] = i2;
            sh_nf = nf;
        }
        __syncwarp();
    }
    const int nfree = sh_nf;
    __syncwarp();

    // --------- Phase B: Dijkstra augmentation for free rows (round-6 body) --
    for (int fidx = 0; fidx < nfree; fidx++) {
        const int cur = freeL[fidx];
        // round init of own segment (constant indices only)
        #pragma unroll
        for (int kk = 0; kk < 16; kk++) {
            tshared[base + kk] = ((validMask >> kk) & 1u) ? FINF : FNINF;
            keysh[base + kk] = 0xffffffffu;
            s64s[base + kk] = DINF;
        }
        unsigned scanned = 0;
        double minv = 0.0;
        float minv32 = 0.0f;
        int i = cur;
        int nSR = 0;
        int sink = -1;
        __syncwarp();

        while (true) {
            if (lane == 0) SRs[nSR] = i;
            nSR++;
            float dd32 = minv32 - u32s[i];
            const float* crow = costB + (size_t)i * NPAD + base;

            // load cost segment (global) and gate segment (shared)
            float4 ca = __ldg((const float4*)(crow + 0));
            float4 cb = __ldg((const float4*)(crow + 4));
            float4 cc_ = __ldg((const float4*)(crow + 8));
            float4 cd = __ldg((const float4*)(crow + 12));
            float4 ta = *(const float4*)(tshared + base + 0);
            float4 tb = *(const float4*)(tshared + base + 4);
            float4 tc = *(const float4*)(tshared + base + 8);
            float4 td = *(const float4*)(tshared + base + 12);

            // fp32 gate sweep: (c + dd32) < t
            unsigned candMask = 0;
            if (ca.x + dd32 < ta.x) candMask |= 1u << 0;
            if (ca.y + dd32 < ta.y) candMask |= 1u << 1;
            if (ca.z + dd32 < ta.z) candMask |= 1u << 2;
            if (ca.w + dd32 < ta.w) candMask |= 1u << 3;
            if (cb.x + dd32 < tb.x) candMask |= 1u << 4;
            if (cb.y + dd32 < tb.y) candMask |= 1u << 5;
            if (cb.z + dd32 < tb.z) candMask |= 1u << 6;
            if (cb.w + dd32 < tb.w) candMask |= 1u << 7;
            if (cc_.x + dd32 < tc.x) candMask |= 1u << 8;
            if (cc_.y + dd32 < tc.y) candMask |= 1u << 9;
            if (cc_.z + dd32 < tc.z) candMask |= 1u << 10;
            if (cc_.w + dd32 < tc.w) candMask |= 1u << 11;
            if (cd.x + dd32 < td.x) candMask |= 1u << 12;
            if (cd.y + dd32 < td.y) candMask |= 1u << 13;
            if (cd.z + dd32 < td.z) candMask |= 1u << 14;
            if (cd.w + dd32 < td.w) candMask |= 1u << 15;

            // exact fp64 updates for candidates (dynamic indices -> shared only)
            if (candMask) {
                double dd = minv - u64s[i];
                do {
                    int kk = __ffs(candMask) - 1;
                    candMask &= candMask - 1;
                    int j = base + kk;
                    double r = ((double)__ldg(crow + kk) - v64s[j]) + dd;
                    if (r < s64s[j]) {
                        s64s[j] = r;
                        paths[j] = i;
                        float rf = (float)r;
                        unsigned ub = __float_as_uint(rf + 1.0f);
                        keysh[j] = (ub & 0xfffffe00u) | (unsigned)j;
                        tshared[j] = v32s[j] + (rf + MARGIN);
                    }
                } while (candMask);
            }

            // reload own keys (constant indices), warp min via tree + REDUX
            uint4 k0 = *(const uint4*)(keysh + base + 0);
            uint4 k1 = *(const uint4*)(keysh + base + 4);
            uint4 k2 = *(const uint4*)(keysh + base + 8);
            uint4 k3 = *(const uint4*)(keysh + base + 12);
            unsigned bk = min(min(min(min(k0.x, k0.y), min(k0.z, k0.w)),
                                  min(min(k1.x, k1.y), min(k1.z, k1.w))),
                              min(min(min(k2.x, k2.y), min(k2.z, k2.w)),
                                  min(min(k3.x, k3.y), min(k3.z, k3.w))));
            unsigned mk = __reduce_min_sync(FULLMASK, bk);
            if (mk == 0xffffffffu) { sink = -1; break; }  // defensive

            // approximate argmin column; prefetch its row (own segment)
            int jm_a = (int)(mk & 0x1ffu);
            int r4c_a = row4cols[jm_a];
            if (r4c_a >= 0) {
                const float* pf = costB + (size_t)r4c_a * NPAD + base;
                asm volatile("prefetch.global.L1 [%0];" :: "l"(pf));
            }

            // threshold window (covers 9-bit key quantization + fp32 error + MARGIN)
            float dec = __uint_as_float(mk & 0xfffffe00u);
            unsigned thrKey = (__float_as_uint(dec + 1e-3f) & 0xfffffe00u) | 0x1ffu;

            unsigned resMask = 0;
            if (k0.x <= thrKey) resMask |= 1u << 0;
            if (k0.y <= thrKey) resMask |= 1u << 1;
            if (k0.z <= thrKey) resMask |= 1u << 2;
            if (k0.w <= thrKey) resMask |= 1u << 3;
            if (k1.x <= thrKey) resMask |= 1u << 4;
            if (k1.y <= thrKey) resMask |= 1u << 5;
            if (k1.z <= thrKey) resMask |= 1u << 6;
            if (k1.w <= thrKey) resMask |= 1u << 7;
            if (k2.x <= thrKey) resMask |= 1u << 8;
            if (k2.y <= thrKey) resMask |= 1u << 9;
            if (k2.z <= thrKey) resMask |= 1u << 10;
            if (k2.w <= thrKey) resMask |= 1u << 11;
            if (k3.x <= thrKey) resMask |= 1u << 12;
            if (k3.y <= thrKey) resMask |= 1u << 13;
            if (k3.z <= thrKey) resMask |= 1u << 14;
            if (k3.w <= thrKey) resMask |= 1u << 15;

            unsigned bal1 = __ballot_sync(FULLMASK, resMask != 0);
            unsigned balM = __ballot_sync(FULLMASK, __popc(resMask) > 1);
            int jm;
            int r4c;
            if (balM == 0 && __popc(bal1) == 1) {
                // fast path: unique window candidate == approximate argmin
                jm = jm_a;
                double myv = s64s[base + (jm_a & 15)];   // own-segment read
                minv = __shfl_sync(FULLMASK, myv, jm_a >> 4);
                r4c = r4c_a;
            } else {
                // slow path: exact fp64 resolution (first-index tie-break)
                double bestV = DINF;
                int bestJ = 0x7fffffff;
                unsigned rm = resMask;
                while (rm) {
                    int kk = __ffs(rm) - 1;
                    rm &= rm - 1;
                    int j = base + kk;
                    double sv = s64s[j];
                    if (sv < bestV) { bestV = sv; bestJ = j; }  // ascending j
                }
                #pragma unroll
                for (int off = 16; off > 0; off >>= 1) {
                    double ov = __shfl_down_sync(FULLMASK, bestV, off);
                    int    oj = __shfl_down_sync(FULLMASK, bestJ, off);
                    if (ov < bestV || (ov == bestV && oj < bestJ)) { bestV = ov; bestJ = oj; }
                }
                minv = __shfl_sync(FULLMASK, bestV, 0);
                jm   = __shfl_sync(FULLMASK, bestJ, 0);
                if (jm > 0x1ff) { sink = -1; break; }   // defensive
                r4c = row4cols[jm];
            }
            minv32 = (float)minv;
            // remove column jm (owner lane)
            if (lane == (jm >> 4)) {
                int kk = jm & 15;
                scanned |= (1u << kk);
                tshared[jm] = FNINF;
                keysh[jm] = 0xffffffffu;
            }
            if (r4c < 0) { sink = jm; break; }
            i = r4c;
        }
        __syncwarp();
        if (sink < 0) continue;       // defensive (never taken in valid runs)

        // dual updates (exact fp64)
        for (int s = lane; s < nSR; s += 32) {
            int row = SRs[s];
            double nu = u64s[row] +
                        ((s == 0) ? minv : (minv - s64s[col4rows[row]]));
            u64s[row] = nu;
            u32s[row] = (float)nu;
        }
        {
            unsigned sm2 = scanned;
            while (sm2) {
                int kk = __ffs(sm2) - 1;
                sm2 &= sm2 - 1;
                int j = base + kk;
                double nv = v64s[j] - (minv - s64s[j]);
                v64s[j] = nv;
                v32s[j] = (float)nv;
            }
        }
        __syncwarp();
        if (lane == 0) {
            int j = sink;
            while (true) {
                int ii = paths[j];
                row4cols[j] = ii;
                int t = col4rows[ii];
                col4rows[ii] = j;
                j = t;
                if (ii == cur) break;
            }
        }
        __syncwarp();
    }

    for (int t = lane; t < MM; t += 32) g_map[b * MM + t] = col4rows[t];
}

// ---------------------------------------------------------------------------
// 4) extrapolation + output write
// ---------------------------------------------------------------------------
__global__ void extrap_kernel(const float* __restrict__ p1_boxes,
                              const float* __restrict__ p1_logits,
                              const float* __restrict__ p2_boxes,
                              const float* __restrict__ p2_logits,
                              const float* __restrict__ toff,
                              float* __restrict__ out) {
    int idx = blockIdx.x * blockDim.x + threadIdx.x;
    const int boxTotal = BB * MM * 4;
    const int logTotal = BB * MM * CC;
    if (idx < boxTotal) {
        int d = idx & 3;
        int bi = idx >> 2;
        int b = bi / MM;
        float first  = toff[b * 3 + 1] - toff[b * 3 + 0];
        float second = toff[b * 3 + 2] - toff[b * 3 + 1];
        float factor = second / first;
        int mcol = g_map[bi];
        float b2 = p2_boxes[idx];
        float c1 = p1_boxes[(b * NN + mcol) * 4 + d];
        float val = b2 + (b2 - c1) * factor;
        if (d >= 2) val = fmaxf(val, 0.0f);
        out[idx] = val;
    } else if (idx < boxTotal + logTotal) {
        int t = idx - boxTotal;
        int c = t % CC;
        int bi = t / CC;
        int b = bi / MM;
        int mcol = g_map[bi];
        float l2 = p2_logits[t];
        float l1 = p1_logits[(b * NN + mcol) * CC + c];
        out[idx] = 0.5f * (l2 + l1);
    }
}

// ---------------------------------------------------------------------------
extern "C" void kernel_launch(void* const* d_in, const int* in_sizes, int n_in,
                              void* d_out, int out_size) {
    const float* p1_boxes  = (const float*)d_in[0];
    const float* p1_logits = (const float*)d_in[1];
    const float* p2_boxes  = (const float*)d_in[2];
    const float* p2_logits = (const float*)d_in[3];
    const float* toff      = (const float*)d_in[4];
    float* out = (float*)d_out;

    {
        int total = BB * NN * CC + BB * MM * CC;
        int threads = 256;
        int blocks = (total + threads - 1) / threads;
        sigmoid_kernel<<<blocks, threads>>>(p1_logits, p2_logits);
    }
    {
        dim3 grid(NPAD / 32, (MM + 31) / 32, BB);
        dim3 block(32, 32);
        cost_kernel<<<grid, block>>>(p1_boxes, p2_boxes);
    }
    lsa_kernel<<<BB, 32>>>();
    {
        int total = BB * MM * 4 + BB * MM * CC;
        int threads = 256;
        int blocks = (total + threads - 1) / threads;
        extrap_kernel<<<blocks, threads>>>(p1_boxes, p1_logits, p2_boxes,
                                           p2_logits, toff, out);
    }
}